// round 8
// baseline (speedup 1.0000x reference)
#include <cuda_runtime.h>
#include <math.h>

#define NSTACK 12
#define ZEROOFF 0.001f
#define EPSV 1e-8f
#define CREC 52      // per-step coef record: a[0:12] c[12:24] e[24:36] q[36:48] pop[48] pad->52
#define CS 32        // chunk size (T steps per chunk)
#define NCH 8        // number of chunks (T/CS)

// Fixed shapes (B=32, T=256, V=2048) for scratch sizing.
__device__ float g_interp[32 * 256];
__device__ float g_partd[32 * 4 * 256];          // per (b, blk, t): partial sp.latch_{t-1}
__device__ float g_partn[32 * 4 * 256];          // per (b, blk, t): partial ||latch_{t-1}||^2
__device__ float g_partsp[4];                    // per blk: partial ||sp||^2
__device__ float g_coef[32 * 256 * CREC];        // per (b,t) coefficient record
__device__ float g_achunk[32 * NCH * NSTACK];    // per (b,ch,n): prod of a over chunk
__device__ float g_W[32 * NCH * NSTACK * 2048];  // chunk affine offset  [b][ch][n][v]
__device__ float g_S[32 * NCH * NSTACK * 2048];  // chunk start states   [b][ch][n][v]

__device__ __forceinline__ float dot4(float4 a, float4 b) {
    return a.x * b.x + a.y * b.y + a.z * b.z + a.w * b.w;
}

// ---------------------------------------------------------------------------
// K1: interp[b,t] = cos(latch_enable, x[b,t]).  One WARP per row, MLP=8.
// ---------------------------------------------------------------------------
__global__ void k1_interp(const float* __restrict__ x, const float* __restrict__ le, int V) {
    int row = blockIdx.x * 8 + (threadIdx.x >> 5);
    int lane = threadIdx.x & 31;
    const float4* xp = (const float4*)(x + (size_t)row * V);
    const float4* le4 = (const float4*)le;
    float d = 0.f, n = 0.f, m = 0.f;
    for (int i0 = lane; i0 < V / 4; i0 += 128) {
        float4 xv[4], l[4];
        #pragma unroll
        for (int j = 0; j < 4; j++) { xv[j] = xp[i0 + 32 * j]; l[j] = le4[i0 + 32 * j]; }
        #pragma unroll
        for (int j = 0; j < 4; j++) {
            d += dot4(l[j], xv[j]);
            n += dot4(xv[j], xv[j]);
            m += dot4(l[j], l[j]);
        }
    }
    #pragma unroll
    for (int o = 16; o > 0; o >>= 1) {
        d += __shfl_xor_sync(0xffffffffu, d, o);
        n += __shfl_xor_sync(0xffffffffu, n, o);
        m += __shfl_xor_sync(0xffffffffu, m, o);
    }
    if (lane == 0) {
        float nle = fmaxf(sqrtf(m), EPSV);
        float nx = fmaxf(sqrtf(n), EPSV);
        g_interp[row] = d / (nle * nx);
    }
}

// ---------------------------------------------------------------------------
// K2: latch scan + fused pop partials. grid (4, B), block 128.
// ---------------------------------------------------------------------------
__global__ void k2_latch(const float* __restrict__ x, const float* __restrict__ latch0,
                         const float* __restrict__ sp, float* __restrict__ latches,
                         int T, int V) {
    __shared__ float s_i[256];
    __shared__ float s_wd[256][4];
    __shared__ float s_wn[256][4];
    __shared__ float s_sp[4];
    int b = blockIdx.y;
    int tid = threadIdx.x;
    int lane = tid & 31;
    int w = tid >> 5;
    int v4 = blockIdx.x * blockDim.x + tid;
    int stride4 = V >> 2;

    for (int t = tid; t < T; t += blockDim.x) s_i[t] = g_interp[b * T + t];
    __syncthreads();

    float4 sp4 = ((const float4*)sp)[v4];
    float4 latch = ((const float4*)(latch0 + (size_t)b * V))[v4];
    const float4* xp = (const float4*)(x + (size_t)b * T * V) + v4;
    float4* lp = (float4*)(latches + (size_t)b * T * V) + v4;

    {
        float d = dot4(sp4, latch);
        float n = dot4(latch, latch);
        float m = dot4(sp4, sp4);
        #pragma unroll
        for (int o = 16; o > 0; o >>= 1) {
            d += __shfl_xor_sync(0xffffffffu, d, o);
            n += __shfl_xor_sync(0xffffffffu, n, o);
            m += __shfl_xor_sync(0xffffffffu, m, o);
        }
        if (lane == 0) { s_wd[0][w] = d; s_wn[0][w] = n; s_sp[w] = m; }
    }

    for (int t0 = 0; t0 < T; t0 += 8) {
        float4 xs[8];
        #pragma unroll
        for (int j = 0; j < 8; j++) xs[j] = xp[(size_t)(t0 + j) * stride4];
        float d8[8], n8[8];
        #pragma unroll
        for (int j = 0; j < 8; j++) {
            float i = s_i[t0 + j];
            latch.x = fmaf(i, xs[j].x - latch.x, latch.x);
            latch.y = fmaf(i, xs[j].y - latch.y, latch.y);
            latch.z = fmaf(i, xs[j].z - latch.z, latch.z);
            latch.w = fmaf(i, xs[j].w - latch.w, latch.w);
            lp[(size_t)(t0 + j) * stride4] = latch;
            d8[j] = dot4(sp4, latch);
            n8[j] = dot4(latch, latch);
        }
        #pragma unroll
        for (int o = 16; o > 0; o >>= 1) {
            #pragma unroll
            for (int j = 0; j < 8; j++) {
                d8[j] += __shfl_xor_sync(0xffffffffu, d8[j], o);
                n8[j] += __shfl_xor_sync(0xffffffffu, n8[j], o);
            }
        }
        if (lane == 0) {
            #pragma unroll
            for (int j = 0; j < 8; j++) {
                int t = t0 + j;
                if (t + 1 < T) { s_wd[t + 1][w] = d8[j]; s_wn[t + 1][w] = n8[j]; }
            }
        }
    }
    __syncthreads();
    int pbase = (b * 4 + blockIdx.x) * T;
    for (int t = tid; t < T; t += blockDim.x) {
        g_partd[pbase + t] = s_wd[t][0] + s_wd[t][1] + s_wd[t][2] + s_wd[t][3];
        g_partn[pbase + t] = s_wn[t][0] + s_wn[t][1] + s_wn[t][2] + s_wn[t][3];
    }
    if (b == 0 && tid == 0)
        g_partsp[blockIdx.x] = s_sp[0] + s_sp[1] + s_sp[2] + s_sp[3];
}

// ---------------------------------------------------------------------------
// K4: pops finalize + pointer scan with unnormalized critical chain.
// One warp per batch. Chain: shfl -> mix -> max -> redux-max renorm -> ^5.
// Exact normalization (incl. EPSV) tracked by scalar rho off the chain:
//   v_t = rho_t * u_t;  pw = W*u_next, W=(rho_t*G)^5;
//   rho_{t+1} = W / (W*S + EPSV), S = sum(u_next).
// ---------------------------------------------------------------------------
__global__ void k4_ptr(const float* __restrict__ sharp_ptr, float* __restrict__ pops, int T) {
    const unsigned FULL = 0xffffffffu;
    __shared__ float s_pop[256];
    int b = blockIdx.x;
    int lane = threadIdx.x;

    // finalize pops (was k3b): 8 values per lane
    float sp2 = g_partsp[0] + g_partsp[1] + g_partsp[2] + g_partsp[3];
    float nsp = fmaxf(sqrtf(sp2), EPSV);
    for (int t = lane; t < T; t += 32) {
        float d = 0.f, n = 0.f;
        #pragma unroll
        for (int blk = 0; blk < 4; blk++) {
            d += g_partd[(b * 4 + blk) * T + t];
            n += g_partn[(b * 4 + blk) * T + t];
        }
        float nl = fmaxf(sqrtf(n), EPSV);
        float c = d / (nsp * nl);
        float p = (c > 0.0f) ? c : expm1f(c);
        s_pop[t] = p;
        pops[b * T + t] = p;
    }
    __syncwarp();

    bool active = lane < NSTACK;
    float sharp = sharp_ptr[0];
    bool fast5 = (sharp == 5.0f);
    float* cbase = g_coef + (size_t)b * T * CREC;
    int src_push = (lane + NSTACK - 1) % NSTACK;
    int src_pop = (lane + 1) % NSTACK;

    float u = (lane == 0) ? 1.0f : 0.0f;   // unnormalized pointer direction
    float rho = 1.0f;                      // v = rho * u (exact)
    float Aacc = 1.0f;

    for (int t = 0; t < T; t++) {
        float pop = s_pop[t];
        float push = 1.0f - pop;
        // ---- critical chain ----
        float up = __shfl_sync(FULL, u, src_push);
        float upop = __shfl_sync(FULL, u, src_pop);
        float m = push * up + pop * upop;
        float p = active ? fmaxf(m, 0.0f) : 0.0f;
        unsigned pb = __float_as_uint(p);
        unsigned Mb;
        asm("redux.sync.max.u32 %0, %1, 0xffffffff;" : "=r"(Mb) : "r"(pb));
        float invG = __uint_as_float((254u - ((Mb >> 23) & 0xFFu)) << 23);
        float ph = p * invG;
        float u_next;
        if (fast5) {
            float p2 = ph * ph;
            u_next = p2 * p2 * ph;
        } else {
            u_next = (ph > 0.f) ? powf(ph, sharp) : 0.f;
        }
        // ---- off-chain: exact scale ----
        float S = u_next;
        #pragma unroll
        for (int o = 8; o > 0; o >>= 1) S += __shfl_xor_sync(FULL, S, o);
        float G = __uint_as_float(Mb & 0x7f800000u);
        float rg = rho * G;
        float W;
        if (fast5) {
            float r2 = rg * rg;
            W = r2 * r2 * rg;
        } else {
            W = powf(rg, sharp);
        }
        float rho_next = __fdividef(W, fmaf(W, S, EPSV));
        // ---- outputs (record t) ----
        float vpush = rho * up;
        float vcur = rho * u;
        float a = push * (1.0f - vpush) + pop * (1.0f - vcur);
        float c = push * vpush;
        float e = pop * (ZEROOFF * vcur);
        float q = rho_next * u_next;
        float* cf = cbase + (size_t)t * CREC;
        if (active) {
            cf[lane] = a;
            cf[12 + lane] = c;
            cf[24 + lane] = e;
            cf[36 + lane] = q;
        }
        if (lane == 0) cf[48] = pop;
        Aacc *= a;
        if ((t & (CS - 1)) == CS - 1) {
            if (active) g_achunk[(b * NCH + (t >> 5)) * NSTACK + lane] = Aacc;
            Aacc = 1.0f;
        }
        u = u_next;
        rho = rho_next;
    }
}

// ---------------------------------------------------------------------------
// K6 (pass 1): replay each chunk from st=0 -> chunk affine offset W.
// grid (4, NCH, B), block 256. Last chunk's W is never consumed -> skipped.
// ---------------------------------------------------------------------------
__global__ void __launch_bounds__(256)
k6_pass1(const float* __restrict__ x, int T, int V) {
    __shared__ __align__(16) float s_c[CS * CREC];
    int b = blockIdx.z, ch = blockIdx.y;
    if (ch == NCH - 1) return;   // W[last] unused
    int t0 = ch * CS;
    const float4* cg = (const float4*)(g_coef + ((size_t)b * T + t0) * CREC);
    float4* cs4 = (float4*)s_c;
    for (int i = threadIdx.x; i < CS * (CREC / 4); i += blockDim.x) cs4[i] = cg[i];
    __syncthreads();

    int col = blockIdx.x * blockDim.x + threadIdx.x;
    int s2 = V >> 1;
    const float2* xp = (const float2*)(x + (size_t)b * T * V) + (size_t)t0 * s2 + col;

    float stx[NSTACK], sty[NSTACK];
    #pragma unroll
    for (int n = 0; n < NSTACK; n++) { stx[n] = 0.f; sty[n] = 0.f; }

    float2 xbuf[4];
    #pragma unroll
    for (int j = 0; j < 4; j++) xbuf[j] = xp[(size_t)j * s2];

    for (int tt = 0; tt < CS; tt += 4) {
        #pragma unroll
        for (int j = 0; j < 4; j++) {
            int t = tt + j;
            float2 xv = xbuf[j];
            int tpre = (t + 4 < CS) ? t + 4 : CS - 1;
            xbuf[j] = xp[(size_t)tpre * s2];
            const float4* cf4 = (const float4*)(s_c + t * CREC);
            float a[12], c[12], e[12];
            *(float4*)&a[0] = cf4[0]; *(float4*)&a[4] = cf4[1]; *(float4*)&a[8] = cf4[2];
            *(float4*)&c[0] = cf4[3]; *(float4*)&c[4] = cf4[4]; *(float4*)&c[8] = cf4[5];
            *(float4*)&e[0] = cf4[6]; *(float4*)&e[4] = cf4[7]; *(float4*)&e[8] = cf4[8];
            #pragma unroll
            for (int n = 0; n < NSTACK; n++) {
                float wx = fmaf(c[n], xv.x, e[n]);
                float wy = fmaf(c[n], xv.y, e[n]);
                stx[n] = fmaf(a[n], stx[n], wx);
                sty[n] = fmaf(a[n], sty[n], wy);
            }
        }
    }
    float2* Wp = (float2*)g_W + ((size_t)(b * NCH + ch) * NSTACK) * s2 + col;
    #pragma unroll
    for (int n = 0; n < NSTACK; n++) {
        float2 w2; w2.x = stx[n]; w2.y = sty[n];
        Wp[(size_t)n * s2] = w2;
    }
}

// ---------------------------------------------------------------------------
// K7 (combine): S[0]=ZEROOFF; S[ch+1] = A[ch]*S[ch] + W[ch]. grid (4, B).
// ---------------------------------------------------------------------------
__global__ void __launch_bounds__(256)
k7_combine(int V) {
    __shared__ float sA[NCH][NSTACK];
    int b = blockIdx.y;
    if (threadIdx.x < NCH * NSTACK)
        sA[threadIdx.x / NSTACK][threadIdx.x % NSTACK] = g_achunk[b * NCH * NSTACK + threadIdx.x];
    __syncthreads();
    int col = blockIdx.x * blockDim.x + threadIdx.x;
    int s2 = V >> 1;
    float sx[NSTACK], sy[NSTACK];
    #pragma unroll
    for (int n = 0; n < NSTACK; n++) { sx[n] = ZEROOFF; sy[n] = ZEROOFF; }
    float2* Sp = (float2*)g_S + ((size_t)b * NCH * NSTACK) * s2 + col;
    const float2* Wp = (const float2*)g_W + ((size_t)b * NCH * NSTACK) * s2 + col;
    #pragma unroll
    for (int ch = 0; ch < NCH; ch++) {
        #pragma unroll
        for (int n = 0; n < NSTACK; n++) {
            float2 s2v; s2v.x = sx[n]; s2v.y = sy[n];
            Sp[(size_t)(ch * NSTACK + n) * s2] = s2v;
        }
        if (ch < NCH - 1) {
            float2 w[NSTACK];
            #pragma unroll
            for (int n = 0; n < NSTACK; n++) w[n] = Wp[(size_t)(ch * NSTACK + n) * s2];
            #pragma unroll
            for (int n = 0; n < NSTACK; n++) {
                float A = sA[ch][n];
                sx[n] = fmaf(A, sx[n], w[n].x);
                sy[n] = fmaf(A, sy[n], w[n].y);
            }
        }
    }
}

// ---------------------------------------------------------------------------
// K8 (pass 2): replay each chunk from its start state, writing outs/tops.
// grid (4, NCH, B), block 256.
// ---------------------------------------------------------------------------
__global__ void __launch_bounds__(256)
k8_pass2(const float* __restrict__ x, float* __restrict__ outs,
         float* __restrict__ tops, int T, int V) {
    __shared__ __align__(16) float s_c[CS * CREC];
    int b = blockIdx.z, ch = blockIdx.y;
    int t0 = ch * CS;
    const float4* cg = (const float4*)(g_coef + ((size_t)b * T + t0) * CREC);
    float4* cs4 = (float4*)s_c;
    for (int i = threadIdx.x; i < CS * (CREC / 4); i += blockDim.x) cs4[i] = cg[i];
    __syncthreads();

    int col = blockIdx.x * blockDim.x + threadIdx.x;
    int s2 = V >> 1;
    const float2* xp = (const float2*)(x + (size_t)b * T * V) + (size_t)t0 * s2 + col;
    float2* op = (float2*)(outs + (size_t)b * T * V) + (size_t)t0 * s2 + col;
    float2* tp = (float2*)(tops + (size_t)b * T * V) + (size_t)t0 * s2 + col;

    float stx[NSTACK], sty[NSTACK];
    const float2* Sp = (const float2*)g_S + ((size_t)(b * NCH + ch) * NSTACK) * s2 + col;
    #pragma unroll
    for (int n = 0; n < NSTACK; n++) {
        float2 s2v = Sp[(size_t)n * s2];
        stx[n] = s2v.x; sty[n] = s2v.y;
    }

    float2 xbuf[4];
    #pragma unroll
    for (int j = 0; j < 4; j++) xbuf[j] = xp[(size_t)j * s2];

    for (int tt = 0; tt < CS; tt += 4) {
        #pragma unroll
        for (int j = 0; j < 4; j++) {
            int t = tt + j;
            float2 xv = xbuf[j];
            int tpre = (t + 4 < CS) ? t + 4 : CS - 1;
            xbuf[j] = xp[(size_t)tpre * s2];
            const float4* cf4 = (const float4*)(s_c + t * CREC);
            float a[12], c[12], e[12], q[12];
            *(float4*)&a[0] = cf4[0]; *(float4*)&a[4] = cf4[1]; *(float4*)&a[8] = cf4[2];
            *(float4*)&c[0] = cf4[3]; *(float4*)&c[4] = cf4[4]; *(float4*)&c[8] = cf4[5];
            *(float4*)&e[0] = cf4[6]; *(float4*)&e[4] = cf4[7]; *(float4*)&e[8] = cf4[8];
            *(float4*)&q[0] = cf4[9]; *(float4*)&q[4] = cf4[10]; *(float4*)&q[8] = cf4[11];
            float pop = cf4[12].x;
            float topx = 0.f, topy = 0.f;
            #pragma unroll
            for (int n = 0; n < NSTACK; n++) {
                float wx = fmaf(c[n], xv.x, e[n]);
                float wy = fmaf(c[n], xv.y, e[n]);
                stx[n] = fmaf(a[n], stx[n], wx);
                sty[n] = fmaf(a[n], sty[n], wy);
                topx = fmaf(stx[n], q[n], topx);
                topy = fmaf(sty[n], q[n], topy);
            }
            float2 o2; o2.x = pop * topx; o2.y = pop * topy;
            float2 t2; t2.x = topx; t2.y = topy;
            op[(size_t)t * s2] = o2;
            tp[(size_t)t * s2] = t2;
        }
    }
}

// ---------------------------------------------------------------------------
// Launch (6 kernels). Output layout: [outs BTV][latches BTV][pops BT][tops BTV]
// ---------------------------------------------------------------------------
extern "C" void kernel_launch(void* const* d_in, const int* in_sizes, int n_in,
                              void* d_out, int out_size) {
    const float* x = (const float*)d_in[0];
    const float* sp = (const float*)d_in[1];
    const float* shp = (const float*)d_in[2];
    const float* le = (const float*)d_in[3];
    const float* l0 = (const float*)d_in[4];

    int V = in_sizes[1];
    int B = in_sizes[4] / V;
    int T = in_sizes[0] / in_sizes[4];

    float* out = (float*)d_out;
    size_t btv = (size_t)B * T * V;
    float* outs = out;
    float* latches = out + btv;
    float* pops = out + 2 * btv;
    float* tops = out + 2 * btv + (size_t)B * T;

    k1_interp<<<B * T / 8, 256>>>(x, le, V);
    dim3 g2(4, B);
    k2_latch<<<g2, 128>>>(x, l0, sp, latches, T, V);
    k4_ptr<<<B, 32>>>(shp, pops, T);
    dim3 g6(V / 512, NCH, B);
    k6_pass1<<<g6, 256>>>(x, T, V);
    dim3 g7(V / 512, B);
    k7_combine<<<g7, 256>>>(V);
    dim3 g8(V / 512, NCH, B);
    k8_pass2<<<g8, 256>>>(x, outs, tops, T, V);
}

// round 9
// speedup vs baseline: 1.0011x; 1.0011x over previous
#include <cuda_runtime.h>
#include <math.h>

#define NSTACK 12
#define ZEROOFF 0.001f
#define EPSV 1e-8f
#define CREC 52      // per-step coef record: a[0:12] c[12:24] e[24:36] q[36:48] pop[48] pad->52
#define CS 32        // chunk size (T steps per chunk)
#define NCH 8        // number of chunks (T/CS)

// Fixed shapes (B=32, T=256, V=2048) for scratch sizing.
__device__ float g_interp[32 * 256];
__device__ float g_partd[32 * 4 * 256];          // per (b, blk, t): partial sp.latch_{t-1}
__device__ float g_partn[32 * 4 * 256];          // per (b, blk, t): partial ||latch_{t-1}||^2
__device__ float g_partsp[4];                    // per blk: partial ||sp||^2
__device__ float g_coef[32 * 256 * CREC];        // per (b,t) coefficient record
__device__ float g_achunk[32 * NCH * NSTACK];    // per (b,ch,n): prod of a over chunk
__device__ float g_W[32 * NCH * NSTACK * 2048];  // chunk affine offset  [b][ch][n][v]

__device__ __forceinline__ float dot4(float4 a, float4 b) {
    return a.x * b.x + a.y * b.y + a.z * b.z + a.w * b.w;
}

// ---------------------------------------------------------------------------
// K1: interp[b,t] = cos(latch_enable, x[b,t]).  One WARP per row, MLP=8.
// ---------------------------------------------------------------------------
__global__ void k1_interp(const float* __restrict__ x, const float* __restrict__ le, int V) {
    int row = blockIdx.x * 8 + (threadIdx.x >> 5);
    int lane = threadIdx.x & 31;
    const float4* xp = (const float4*)(x + (size_t)row * V);
    const float4* le4 = (const float4*)le;
    float d = 0.f, n = 0.f, m = 0.f;
    for (int i0 = lane; i0 < V / 4; i0 += 128) {
        float4 xv[4], l[4];
        #pragma unroll
        for (int j = 0; j < 4; j++) { xv[j] = xp[i0 + 32 * j]; l[j] = le4[i0 + 32 * j]; }
        #pragma unroll
        for (int j = 0; j < 4; j++) {
            d += dot4(l[j], xv[j]);
            n += dot4(xv[j], xv[j]);
            m += dot4(l[j], l[j]);
        }
    }
    #pragma unroll
    for (int o = 16; o > 0; o >>= 1) {
        d += __shfl_xor_sync(0xffffffffu, d, o);
        n += __shfl_xor_sync(0xffffffffu, n, o);
        m += __shfl_xor_sync(0xffffffffu, m, o);
    }
    if (lane == 0) {
        float nle = fmaxf(sqrtf(m), EPSV);
        float nx = fmaxf(sqrtf(n), EPSV);
        g_interp[row] = d / (nle * nx);
    }
}

// ---------------------------------------------------------------------------
// K2: latch scan + fused pop partials. grid (4, B), block 128.
// ---------------------------------------------------------------------------
__global__ void k2_latch(const float* __restrict__ x, const float* __restrict__ latch0,
                         const float* __restrict__ sp, float* __restrict__ latches,
                         int T, int V) {
    __shared__ float s_i[256];
    __shared__ float s_wd[256][4];
    __shared__ float s_wn[256][4];
    __shared__ float s_sp[4];
    int b = blockIdx.y;
    int tid = threadIdx.x;
    int lane = tid & 31;
    int w = tid >> 5;
    int v4 = blockIdx.x * blockDim.x + tid;
    int stride4 = V >> 2;

    for (int t = tid; t < T; t += blockDim.x) s_i[t] = g_interp[b * T + t];
    __syncthreads();

    float4 sp4 = ((const float4*)sp)[v4];
    float4 latch = ((const float4*)(latch0 + (size_t)b * V))[v4];
    const float4* xp = (const float4*)(x + (size_t)b * T * V) + v4;
    float4* lp = (float4*)(latches + (size_t)b * T * V) + v4;

    {
        float d = dot4(sp4, latch);
        float n = dot4(latch, latch);
        float m = dot4(sp4, sp4);
        #pragma unroll
        for (int o = 16; o > 0; o >>= 1) {
            d += __shfl_xor_sync(0xffffffffu, d, o);
            n += __shfl_xor_sync(0xffffffffu, n, o);
            m += __shfl_xor_sync(0xffffffffu, m, o);
        }
        if (lane == 0) { s_wd[0][w] = d; s_wn[0][w] = n; s_sp[w] = m; }
    }

    for (int t0 = 0; t0 < T; t0 += 8) {
        float4 xs[8];
        #pragma unroll
        for (int j = 0; j < 8; j++) xs[j] = xp[(size_t)(t0 + j) * stride4];
        float d8[8], n8[8];
        #pragma unroll
        for (int j = 0; j < 8; j++) {
            float i = s_i[t0 + j];
            latch.x = fmaf(i, xs[j].x - latch.x, latch.x);
            latch.y = fmaf(i, xs[j].y - latch.y, latch.y);
            latch.z = fmaf(i, xs[j].z - latch.z, latch.z);
            latch.w = fmaf(i, xs[j].w - latch.w, latch.w);
            lp[(size_t)(t0 + j) * stride4] = latch;
            d8[j] = dot4(sp4, latch);
            n8[j] = dot4(latch, latch);
        }
        #pragma unroll
        for (int o = 16; o > 0; o >>= 1) {
            #pragma unroll
            for (int j = 0; j < 8; j++) {
                d8[j] += __shfl_xor_sync(0xffffffffu, d8[j], o);
                n8[j] += __shfl_xor_sync(0xffffffffu, n8[j], o);
            }
        }
        if (lane == 0) {
            #pragma unroll
            for (int j = 0; j < 8; j++) {
                int t = t0 + j;
                if (t + 1 < T) { s_wd[t + 1][w] = d8[j]; s_wn[t + 1][w] = n8[j]; }
            }
        }
    }
    __syncthreads();
    int pbase = (b * 4 + blockIdx.x) * T;
    for (int t = tid; t < T; t += blockDim.x) {
        g_partd[pbase + t] = s_wd[t][0] + s_wd[t][1] + s_wd[t][2] + s_wd[t][3];
        g_partn[pbase + t] = s_wn[t][0] + s_wn[t][1] + s_wn[t][2] + s_wn[t][3];
    }
    if (b == 0 && tid == 0)
        g_partsp[blockIdx.x] = s_sp[0] + s_sp[1] + s_sp[2] + s_sp[3];
}

// ---------------------------------------------------------------------------
// K4: pops finalize + pointer scan with unnormalized critical chain
// (exact normalization tracked off-chain by scalar rho).
// ---------------------------------------------------------------------------
__global__ void k4_ptr(const float* __restrict__ sharp_ptr, float* __restrict__ pops, int T) {
    const unsigned FULL = 0xffffffffu;
    __shared__ float s_pop[256];
    int b = blockIdx.x;
    int lane = threadIdx.x;

    float sp2 = g_partsp[0] + g_partsp[1] + g_partsp[2] + g_partsp[3];
    float nsp = fmaxf(sqrtf(sp2), EPSV);
    for (int t = lane; t < T; t += 32) {
        float d = 0.f, n = 0.f;
        #pragma unroll
        for (int blk = 0; blk < 4; blk++) {
            d += g_partd[(b * 4 + blk) * T + t];
            n += g_partn[(b * 4 + blk) * T + t];
        }
        float nl = fmaxf(sqrtf(n), EPSV);
        float c = d / (nsp * nl);
        float p = (c > 0.0f) ? c : expm1f(c);
        s_pop[t] = p;
        pops[b * T + t] = p;
    }
    __syncwarp();

    bool active = lane < NSTACK;
    float sharp = sharp_ptr[0];
    bool fast5 = (sharp == 5.0f);
    float* cbase = g_coef + (size_t)b * T * CREC;
    int src_push = (lane + NSTACK - 1) % NSTACK;
    int src_pop = (lane + 1) % NSTACK;

    float u = (lane == 0) ? 1.0f : 0.0f;
    float rho = 1.0f;
    float Aacc = 1.0f;

    for (int t = 0; t < T; t++) {
        float pop = s_pop[t];
        float push = 1.0f - pop;
        float up = __shfl_sync(FULL, u, src_push);
        float upop = __shfl_sync(FULL, u, src_pop);
        float m = push * up + pop * upop;
        float p = active ? fmaxf(m, 0.0f) : 0.0f;
        unsigned pb = __float_as_uint(p);
        unsigned Mb;
        asm("redux.sync.max.u32 %0, %1, 0xffffffff;" : "=r"(Mb) : "r"(pb));
        float invG = __uint_as_float((254u - ((Mb >> 23) & 0xFFu)) << 23);
        float ph = p * invG;
        float u_next;
        if (fast5) {
            float p2 = ph * ph;
            u_next = p2 * p2 * ph;
        } else {
            u_next = (ph > 0.f) ? powf(ph, sharp) : 0.f;
        }
        float S = u_next;
        #pragma unroll
        for (int o = 8; o > 0; o >>= 1) S += __shfl_xor_sync(FULL, S, o);
        float G = __uint_as_float(Mb & 0x7f800000u);
        float rg = rho * G;
        float W;
        if (fast5) {
            float r2 = rg * rg;
            W = r2 * r2 * rg;
        } else {
            W = powf(rg, sharp);
        }
        float rho_next = __fdividef(W, fmaf(W, S, EPSV));
        float vpush = rho * up;
        float vcur = rho * u;
        float a = push * (1.0f - vpush) + pop * (1.0f - vcur);
        float c = push * vpush;
        float e = pop * (ZEROOFF * vcur);
        float q = rho_next * u_next;
        float* cf = cbase + (size_t)t * CREC;
        if (active) {
            cf[lane] = a;
            cf[12 + lane] = c;
            cf[24 + lane] = e;
            cf[36 + lane] = q;
        }
        if (lane == 0) cf[48] = pop;
        Aacc *= a;
        if ((t & (CS - 1)) == CS - 1) {
            if (active) g_achunk[(b * NCH + (t >> 5)) * NSTACK + lane] = Aacc;
            Aacc = 1.0f;
        }
        u = u_next;
        rho = rho_next;
    }
}

// ---------------------------------------------------------------------------
// K6 (pass 1): replay each chunk from st=0 -> chunk affine offset W.
// Grouped coefficient loads (4 slots per float4) keep register count low.
// grid (4, NCH-1, B), block 256.  Last chunk's W is never consumed.
// ---------------------------------------------------------------------------
__global__ void __launch_bounds__(256)
k6_pass1(const float* __restrict__ x, int T, int V) {
    __shared__ __align__(16) float s_c[CS * CREC];
    int b = blockIdx.z, ch = blockIdx.y;
    int t0 = ch * CS;
    const float4* cg = (const float4*)(g_coef + ((size_t)b * T + t0) * CREC);
    float4* cs4 = (float4*)s_c;
    for (int i = threadIdx.x; i < CS * (CREC / 4); i += blockDim.x) cs4[i] = cg[i];
    __syncthreads();

    int col = blockIdx.x * blockDim.x + threadIdx.x;
    int s2 = V >> 1;
    const float2* xp = (const float2*)(x + (size_t)b * T * V) + (size_t)t0 * s2 + col;

    float stx[NSTACK], sty[NSTACK];
    #pragma unroll
    for (int n = 0; n < NSTACK; n++) { stx[n] = 0.f; sty[n] = 0.f; }

    float2 xbuf[4];
    #pragma unroll
    for (int j = 0; j < 4; j++) xbuf[j] = xp[(size_t)j * s2];

    for (int tt = 0; tt < CS; tt += 4) {
        #pragma unroll
        for (int j = 0; j < 4; j++) {
            int t = tt + j;
            float2 xv = xbuf[j];
            int tpre = (t + 4 < CS) ? t + 4 : CS - 1;
            xbuf[j] = xp[(size_t)tpre * s2];
            const float4* cf4 = (const float4*)(s_c + t * CREC);
            #pragma unroll
            for (int g = 0; g < 3; g++) {
                float a4[4], c4[4], e4[4];
                *(float4*)a4 = cf4[g];
                *(float4*)c4 = cf4[3 + g];
                *(float4*)e4 = cf4[6 + g];
                #pragma unroll
                for (int k = 0; k < 4; k++) {
                    int n = 4 * g + k;
                    stx[n] = fmaf(a4[k], stx[n], fmaf(c4[k], xv.x, e4[k]));
                    sty[n] = fmaf(a4[k], sty[n], fmaf(c4[k], xv.y, e4[k]));
                }
            }
        }
    }
    float2* Wp = (float2*)g_W + ((size_t)(b * NCH + ch) * NSTACK) * s2 + col;
    #pragma unroll
    for (int n = 0; n < NSTACK; n++) {
        float2 w2; w2.x = stx[n]; w2.y = sty[n];
        Wp[(size_t)n * s2] = w2;
    }
}

// ---------------------------------------------------------------------------
// K8 (pass 2, fused combine): computes its chunk start state from W/A chain,
// then replays the chunk writing outs/tops. grid (4, NCH, B), block 256.
// ---------------------------------------------------------------------------
__global__ void __launch_bounds__(256)
k8_pass2(const float* __restrict__ x, float* __restrict__ outs,
         float* __restrict__ tops, int T, int V) {
    __shared__ __align__(16) float s_c[CS * CREC];
    __shared__ float sA[NCH - 1][NSTACK];
    int b = blockIdx.z, ch = blockIdx.y;
    int t0 = ch * CS;
    const float4* cg = (const float4*)(g_coef + ((size_t)b * T + t0) * CREC);
    float4* cs4 = (float4*)s_c;
    for (int i = threadIdx.x; i < CS * (CREC / 4); i += blockDim.x) cs4[i] = cg[i];
    if (threadIdx.x < (NCH - 1) * NSTACK)
        sA[threadIdx.x / NSTACK][threadIdx.x % NSTACK] =
            g_achunk[b * NCH * NSTACK + threadIdx.x];
    __syncthreads();

    int col = blockIdx.x * blockDim.x + threadIdx.x;
    int s2 = V >> 1;
    const float2* xp = (const float2*)(x + (size_t)b * T * V) + (size_t)t0 * s2 + col;
    float2* op = (float2*)(outs + (size_t)b * T * V) + (size_t)t0 * s2 + col;
    float2* tp = (float2*)(tops + (size_t)b * T * V) + (size_t)t0 * s2 + col;

    // combine: start state = fold of A/W over chunks < ch
    float stx[NSTACK], sty[NSTACK];
    #pragma unroll
    for (int n = 0; n < NSTACK; n++) { stx[n] = ZEROOFF; sty[n] = ZEROOFF; }
    for (int j = 0; j < ch; j++) {
        const float2* Wp = (const float2*)g_W + ((size_t)(b * NCH + j) * NSTACK) * s2 + col;
        float2 w[NSTACK];
        #pragma unroll
        for (int n = 0; n < NSTACK; n++) w[n] = Wp[(size_t)n * s2];
        #pragma unroll
        for (int n = 0; n < NSTACK; n++) {
            float A = sA[j][n];
            stx[n] = fmaf(A, stx[n], w[n].x);
            sty[n] = fmaf(A, sty[n], w[n].y);
        }
    }

    float2 xbuf[4];
    #pragma unroll
    for (int j = 0; j < 4; j++) xbuf[j] = xp[(size_t)j * s2];

    for (int tt = 0; tt < CS; tt += 4) {
        #pragma unroll
        for (int j = 0; j < 4; j++) {
            int t = tt + j;
            float2 xv = xbuf[j];
            int tpre = (t + 4 < CS) ? t + 4 : CS - 1;
            xbuf[j] = xp[(size_t)tpre * s2];
            const float4* cf4 = (const float4*)(s_c + t * CREC);
            float topx = 0.f, topy = 0.f;
            #pragma unroll
            for (int g = 0; g < 3; g++) {
                float a4[4], c4[4], e4[4], q4[4];
                *(float4*)a4 = cf4[g];
                *(float4*)c4 = cf4[3 + g];
                *(float4*)e4 = cf4[6 + g];
                *(float4*)q4 = cf4[9 + g];
                #pragma unroll
                for (int k = 0; k < 4; k++) {
                    int n = 4 * g + k;
                    stx[n] = fmaf(a4[k], stx[n], fmaf(c4[k], xv.x, e4[k]));
                    sty[n] = fmaf(a4[k], sty[n], fmaf(c4[k], xv.y, e4[k]));
                    topx = fmaf(stx[n], q4[k], topx);
                    topy = fmaf(sty[n], q4[k], topy);
                }
            }
            float pop = s_c[t * CREC + 48];
            float2 o2; o2.x = pop * topx; o2.y = pop * topy;
            float2 t2; t2.x = topx; t2.y = topy;
            op[(size_t)t * s2] = o2;
            tp[(size_t)t * s2] = t2;
        }
    }
}

// ---------------------------------------------------------------------------
// Launch (5 kernels). Output layout: [outs BTV][latches BTV][pops BT][tops BTV]
// ---------------------------------------------------------------------------
extern "C" void kernel_launch(void* const* d_in, const int* in_sizes, int n_in,
                              void* d_out, int out_size) {
    const float* x = (const float*)d_in[0];
    const float* sp = (const float*)d_in[1];
    const float* shp = (const float*)d_in[2];
    const float* le = (const float*)d_in[3];
    const float* l0 = (const float*)d_in[4];

    int V = in_sizes[1];
    int B = in_sizes[4] / V;
    int T = in_sizes[0] / in_sizes[4];

    float* out = (float*)d_out;
    size_t btv = (size_t)B * T * V;
    float* outs = out;
    float* latches = out + btv;
    float* pops = out + 2 * btv;
    float* tops = out + 2 * btv + (size_t)B * T;

    k1_interp<<<B * T / 8, 256>>>(x, le, V);
    dim3 g2(4, B);
    k2_latch<<<g2, 128>>>(x, l0, sp, latches, T, V);
    k4_ptr<<<B, 32>>>(shp, pops, T);
    dim3 g6(V / 512, NCH - 1, B);
    k6_pass1<<<g6, 256>>>(x, T, V);
    dim3 g8(V / 512, NCH, B);
    k8_pass2<<<g8, 256>>>(x, outs, tops, T, V);
}